// round 6
// baseline (speedup 1.0000x reference)
#include <cuda_runtime.h>
#include <cstdint>

#define U_DIM 7
#define V_DIM 7
#define H_DIM 48
#define W_DIM 48
#define C_IN 8
#define OC 8
#define TH 8          // h rows per block tile
#define TCOLS 24      // thread columns, 2 pixels each
#define NT_HALF 192   // threads per c-group
#define NTHREADS 384  // two c-groups
#define XSTRIDE 56    // smem row stride (floats)
#define XOFF 4        // data at col w+XOFF; halo zeros at w=-1 / w=48
#define CH_STRIDE (U_DIM * V_DIM * H_DIM * W_DIM)

#define SX_FLOATS (C_IN * (TH + 2) * XSTRIDE)          // 4480 floats (17.5 KB)
#define SMEM_BYTES ((SX_FLOATS + 81 * 64) * 4)         // 38272 B

__device__ __forceinline__ unsigned long long pack2(float v) {
    unsigned long long r;
    asm("mov.b64 %0, {%1, %1};" : "=l"(r) : "f"(v));
    return r;
}
__device__ __forceinline__ void ffma2(unsigned long long& acc,
                                      unsigned long long a,
                                      unsigned long long b) {
    asm("fma.rn.f32x2 %0, %1, %2, %0;" : "+l"(acc) : "l"(a), "l"(b));
}
__device__ __forceinline__ void unpack2(unsigned long long v, float& lo, float& hi) {
    asm("mov.b64 {%0, %1}, %2;" : "=f"(lo), "=f"(hi) : "l"(v));
}

// x:    [2][8][7][7][48][48] fp32
// conv: [8][648]  (oc, tap-major/channel-minor), tap = ((i0*3+i1)*3+i2)*3+i3
// bias: [8]
// out:  [2][8][7][7][48][48]
__global__ __launch_bounds__(NTHREADS, 4) void conv4d_kernel(
    const float* __restrict__ x,
    const float* __restrict__ conv,
    const float* __restrict__ bias,
    float* __restrict__ out)
{
    extern __shared__ float smem[];
    float (*sX)[TH + 2][XSTRIDE] = (float (*)[TH + 2][XSTRIDE])smem;  // [8][10][56]
    float* sWt = smem + SX_FLOATS;                                     // [tap][c][o]

    const int tid = threadIdx.x;
    const int h0  = blockIdx.x * TH;
    const int uv  = blockIdx.y;
    const int u   = uv / V_DIM;
    const int v   = uv % V_DIM;
    const int b   = blockIdx.z;

    // stage weights transposed (covered by first barrier in loop)
    #pragma unroll 4
    for (int idx = tid; idx < 81 * 64; idx += NTHREADS) {
        const int tap = idx >> 6;
        const int c   = (idx >> 3) & 7;
        const int o   = idx & 7;
        sWt[idx] = conv[o * 648 + tap * 8 + c];
    }
    // zero w-halo cols (always globally OOB)
    if (tid < C_IN * (TH + 2)) {
        const int cl = tid / (TH + 2);
        const int r  = tid % (TH + 2);
        sX[cl][r][XOFF - 1]     = 0.0f;
        sX[cl][r][XOFF + W_DIM] = 0.0f;
    }

    // valid (i0,i1) phases
    int ph_off[9], ph_tap[9];
    int nph = 0;
    #pragma unroll
    for (int i0 = 0; i0 < 3; i0++) {
        const int uu = u + i0 - 1;
        if (uu < 0 || uu >= U_DIM) continue;
        #pragma unroll
        for (int i1 = 0; i1 < 3; i1++) {
            const int vv = v + i1 - 1;
            if (vv < 0 || vv >= V_DIM) continue;
            ph_off[nph] = (uu * V_DIM + vv) * (H_DIM * W_DIM);
            ph_tap[nph] = (i0 * 3 + i1) * 9;
            nph++;
        }
    }

    const float* xb = x + (size_t)b * C_IN * CH_STRIDE;

    const int cg    = tid / NT_HALF;        // c-group: 0 -> c 0..3, 1 -> c 4..7
    const int ltid  = tid - cg * NT_HALF;   // 0..191
    const int row   = ltid / TCOLS;         // 0..7
    const int tcol  = ltid % TCOLS;         // 0..23
    const int wbase = tcol * 2;             // 0,2,...,46

    // cp.async slots: 960 float4 (8ch x 10 rows x 12) over 384 threads -> <=3 each
    int pf_goff[3];
    uint32_t pf_sa[3];
    int pf_sz[3];
    bool pf_on[3];
    #pragma unroll
    for (int k = 0; k < 3; k++) {
        const int idx = tid + k * NTHREADS;
        pf_on[k] = (idx < 960);
        const int cidx = pf_on[k] ? idx : 0;
        const int cl  = cidx / 120;
        const int rem = cidx - cl * 120;
        const int r   = rem / 12;
        const int q   = rem - r * 12;
        const int gh  = h0 + r - 1;
        const bool ok = (gh >= 0) && (gh < H_DIM);
        pf_goff[k] = cl * CH_STRIDE + (ok ? gh : 0) * W_DIM + q * 4;
        pf_sa[k]   = (uint32_t)__cvta_generic_to_shared(&sX[cl][r][XOFF + q * 4]);
        pf_sz[k]   = ok ? 16 : 0;
    }

    unsigned long long acc[2][4];   // [pixel][oc-pair]
    #pragma unroll
    for (int p = 0; p < 2; p++)
        #pragma unroll
        for (int op = 0; op < 4; op++)
            acc[p][op] = 0ULL;

    for (int p = 0; p < nph; p++) {
        __syncthreads();   // previous compute done before overwrite
        const float* src = xb + ph_off[p];
        #pragma unroll
        for (int k = 0; k < 3; k++) {
            if (pf_on[k])
                asm volatile("cp.async.ca.shared.global [%0], [%1], 16, %2;"
                             :: "r"(pf_sa[k]), "l"(src + pf_goff[k]), "r"(pf_sz[k]));
        }
        asm volatile("cp.async.commit_group;");
        asm volatile("cp.async.wait_group 0;");
        __syncthreads();

        const int tapbase = ph_tap[p];

        #pragma unroll
        for (int ci = 0; ci < 4; ci++) {
            const int cl = cg * 4 + ci;
            #pragma unroll
            for (int i2 = 0; i2 < 3; i2++) {
                const float* xr = &sX[cl][row + i2][XOFF - 1 + wbase];
                unsigned long long xq[4];
                xq[0] = pack2(xr[0]);
                xq[1] = pack2(xr[1]);
                xq[2] = pack2(xr[2]);
                xq[3] = pack2(xr[3]);

                #pragma unroll
                for (int i3 = 0; i3 < 3; i3++) {
                    const int tap = tapbase + i2 * 3 + i3;
                    const float* wp = &sWt[(tap * 8 + cl) * 8];
                    const ulonglong2 wA = *(const ulonglong2*)wp;
                    const ulonglong2 wB = *(const ulonglong2*)(wp + 4);
                    #pragma unroll
                    for (int px = 0; px < 2; px++) {
                        const unsigned long long xv = xq[i3 + px];
                        ffma2(acc[px][0], xv, wA.x);
                        ffma2(acc[px][1], xv, wA.y);
                        ffma2(acc[px][2], xv, wB.x);
                        ffma2(acc[px][3], xv, wB.y);
                    }
                }
            }
        }
    }

    // cross-group reduction: group 1 dumps partials into smem (overlaid on sX)
    __syncthreads();
    unsigned long long* scratch = (unsigned long long*)smem;   // 192*8 u64 = 12 KB
    if (cg == 1) {
        #pragma unroll
        for (int p = 0; p < 2; p++)
            #pragma unroll
            for (int op = 0; op < 4; op++)
                scratch[ltid * 8 + p * 4 + op] = acc[p][op];
    }
    __syncthreads();
    if (cg == 0) {
        const int h = h0 + row;
        #pragma unroll
        for (int op = 0; op < 4; op++) {
            float a00, a01, a10, a11, b00, b01, b10, b11;
            unpack2(acc[0][op], a00, a01);
            unpack2(acc[1][op], a10, a11);
            unpack2(scratch[ltid * 8 + 0 * 4 + op], b00, b01);
            unpack2(scratch[ltid * 8 + 1 * 4 + op], b10, b11);
            const int o0 = 2 * op;
            const float bi0 = __ldg(&bias[o0]);
            const float bi1 = __ldg(&bias[o0 + 1]);
            float2 r0, r1;
            r0.x = a00 + b00 + bi0;  r0.y = a10 + b10 + bi0;
            r1.x = a01 + b01 + bi1;  r1.y = a11 + b11 + bi1;
            float* dst0 = &out[((((b * OC + o0) * U_DIM + u) * V_DIM + v) * H_DIM + h) * W_DIM + wbase];
            float* dst1 = &out[((((b * OC + o0 + 1) * U_DIM + u) * V_DIM + v) * H_DIM + h) * W_DIM + wbase];
            *(float2*)dst0 = r0;
            *(float2*)dst1 = r1;
        }
    }
}

extern "C" void kernel_launch(void* const* d_in, const int* in_sizes, int n_in,
                              void* d_out, int out_size)
{
    const float* x    = (const float*)d_in[0];
    const float* conv = (const float*)d_in[1];
    const float* bias = (const float*)d_in[2];
    float* out        = (float*)d_out;

    cudaFuncSetAttribute(conv4d_kernel,
                         cudaFuncAttributeMaxDynamicSharedMemorySize, SMEM_BYTES);

    dim3 grid(H_DIM / TH, U_DIM * V_DIM, 2);   // (6, 49, 2) = 588 blocks
    conv4d_kernel<<<grid, NTHREADS, SMEM_BYTES>>>(x, conv, bias, out);
}

// round 7
// speedup vs baseline: 1.1448x; 1.1448x over previous
#include <cuda_runtime.h>
#include <cstdint>

#define U_DIM 7
#define V_DIM 7
#define H_DIM 48
#define W_DIM 48
#define C_IN 8
#define OC 8
#define TH 8          // h rows per block tile
#define TCOLS 12      // thread columns, 4 pixels each
#define PPT 4
#define NT_HALF 96    // threads per c-group
#define NTHREADS 192  // two c-groups
#define XSTRIDE 56    // smem row stride (floats)
#define XOFF 4        // data at col w+XOFF; halo zeros at w=-1 / w=48
#define CH_STRIDE (U_DIM * V_DIM * H_DIM * W_DIM)

#define SX_FLOATS (C_IN * (TH + 2) * XSTRIDE)          // 4480 floats (17.5 KB)
#define SMEM_BYTES ((SX_FLOATS + 81 * 64) * 4)         // 38656 B

__device__ __forceinline__ unsigned long long pack2(float v) {
    unsigned long long r;
    asm("mov.b64 %0, {%1, %1};" : "=l"(r) : "f"(v));
    return r;
}
__device__ __forceinline__ void ffma2(unsigned long long& acc,
                                      unsigned long long a,
                                      unsigned long long b) {
    asm("fma.rn.f32x2 %0, %1, %2, %0;" : "+l"(acc) : "l"(a), "l"(b));
}
__device__ __forceinline__ void unpack2(unsigned long long v, float& lo, float& hi) {
    asm("mov.b64 {%0, %1}, %2;" : "=f"(lo), "=f"(hi) : "l"(v));
}

// x:    [2][8][7][7][48][48] fp32
// conv: [8][648]  (oc, tap-major/channel-minor), tap = ((i0*3+i1)*3+i2)*3+i3
// bias: [8]
// out:  [2][8][7][7][48][48]
__global__ __launch_bounds__(NTHREADS, 4) void conv4d_kernel(
    const float* __restrict__ x,
    const float* __restrict__ conv,
    const float* __restrict__ bias,
    float* __restrict__ out)
{
    extern __shared__ float smem[];
    float (*sX)[TH + 2][XSTRIDE] = (float (*)[TH + 2][XSTRIDE])smem;  // [8][10][56]
    float* sWt = smem + SX_FLOATS;                                     // [tap][c][o]

    const int tid = threadIdx.x;
    const int h0  = blockIdx.x * TH;
    const int uv  = blockIdx.y;
    const int u   = uv / V_DIM;
    const int v   = uv % V_DIM;
    const int b   = blockIdx.z;

    // stage weights transposed (covered by first barrier in loop)
    #pragma unroll 4
    for (int idx = tid; idx < 81 * 64; idx += NTHREADS) {
        const int tap = idx >> 6;
        const int c   = (idx >> 3) & 7;
        const int o   = idx & 7;
        sWt[idx] = conv[o * 648 + tap * 8 + c];
    }
    // zero w-halo cols (always globally OOB)
    if (tid < C_IN * (TH + 2)) {
        const int cl = tid / (TH + 2);
        const int r  = tid % (TH + 2);
        sX[cl][r][XOFF - 1]     = 0.0f;
        sX[cl][r][XOFF + W_DIM] = 0.0f;
    }

    // valid (i0,i1) phases
    int ph_off[9], ph_tap[9];
    int nph = 0;
    #pragma unroll
    for (int i0 = 0; i0 < 3; i0++) {
        const int uu = u + i0 - 1;
        if (uu < 0 || uu >= U_DIM) continue;
        #pragma unroll
        for (int i1 = 0; i1 < 3; i1++) {
            const int vv = v + i1 - 1;
            if (vv < 0 || vv >= V_DIM) continue;
            ph_off[nph] = (uu * V_DIM + vv) * (H_DIM * W_DIM);
            ph_tap[nph] = (i0 * 3 + i1) * 9;
            nph++;
        }
    }

    const float* xb = x + (size_t)b * C_IN * CH_STRIDE;

    const int cg    = tid / NT_HALF;        // c-group: 0 -> c 0..3, 1 -> c 4..7
    const int ltid  = tid - cg * NT_HALF;   // 0..95
    const int row   = ltid / TCOLS;         // 0..7
    const int tcol  = ltid % TCOLS;         // 0..11
    const int wbase = tcol * PPT;           // 0,4,...,44

    // cp.async slots: 960 float4 (8ch x 10 rows x 12) over 192 threads -> 5 each
    int pf_goff[5];
    uint32_t pf_sa[5];
    int pf_sz[5];
    #pragma unroll
    for (int k = 0; k < 5; k++) {
        const int idx = tid + k * NTHREADS;
        const int cl  = idx / 120;
        const int rem = idx - cl * 120;
        const int r   = rem / 12;
        const int q   = rem - r * 12;
        const int gh  = h0 + r - 1;
        const bool ok = (gh >= 0) && (gh < H_DIM);
        pf_goff[k] = cl * CH_STRIDE + (ok ? gh : 0) * W_DIM + q * 4;
        pf_sa[k]   = (uint32_t)__cvta_generic_to_shared(&sX[cl][r][XOFF + q * 4]);
        pf_sz[k]   = ok ? 16 : 0;
    }

    // acc[px][op]: pixel px 0..3, oc-pair op 0..3 (lanes oc 2op, 2op+1)
    unsigned long long acc[PPT][4];
    #pragma unroll
    for (int p = 0; p < PPT; p++)
        #pragma unroll
        for (int op = 0; op < 4; op++)
            acc[p][op] = 0ULL;

    for (int p = 0; p < nph; p++) {
        __syncthreads();   // previous compute done before overwrite
        const float* src = xb + ph_off[p];
        #pragma unroll
        for (int k = 0; k < 5; k++)
            asm volatile("cp.async.ca.shared.global [%0], [%1], 16, %2;"
                         :: "r"(pf_sa[k]), "l"(src + pf_goff[k]), "r"(pf_sz[k]));
        asm volatile("cp.async.commit_group;");
        asm volatile("cp.async.wait_group 0;");
        __syncthreads();

        const int tapbase = ph_tap[p];

        #pragma unroll
        for (int ci = 0; ci < 4; ci++) {
            const int cl = cg * 4 + ci;
            #pragma unroll
            for (int i2 = 0; i2 < 3; i2++) {
                // window w-1..w+4 -> smem cols (XOFF-1+wbase)..(XOFF+4+wbase)
                const float* xr = &sX[cl][row + i2][0];
                const float2 xa = *(const float2*)(xr + XOFF - 2 + wbase);  // cols w-2,w-1
                const float4 xm = *(const float4*)(xr + XOFF + wbase);      // w..w+3
                const float2 xc = *(const float2*)(xr + XOFF + 4 + wbase);  // w+4,w+5
                unsigned long long xq[6];
                xq[0] = pack2(xa.y);
                xq[1] = pack2(xm.x);
                xq[2] = pack2(xm.y);
                xq[3] = pack2(xm.z);
                xq[4] = pack2(xm.w);
                xq[5] = pack2(xc.x);

                #pragma unroll
                for (int i3 = 0; i3 < 3; i3++) {
                    const int tap = tapbase + i2 * 3 + i3;
                    const float* wp = &sWt[(tap * 8 + cl) * 8];
                    const ulonglong2 wA = *(const ulonglong2*)wp;        // (o0,o1)(o2,o3)
                    const ulonglong2 wB = *(const ulonglong2*)(wp + 4);  // (o4,o5)(o6,o7)
                    #pragma unroll
                    for (int px = 0; px < PPT; px++) {
                        const unsigned long long xv = xq[i3 + px];
                        ffma2(acc[px][0], xv, wA.x);
                        ffma2(acc[px][1], xv, wA.y);
                        ffma2(acc[px][2], xv, wB.x);
                        ffma2(acc[px][3], xv, wB.y);
                    }
                }
            }
        }
    }

    // cross-group reduction: group 1 dumps partials into smem (overlaid on sX)
    __syncthreads();
    unsigned long long* scratch = (unsigned long long*)smem;   // 96*16 u64 = 12 KB
    if (cg == 1) {
        #pragma unroll
        for (int px = 0; px < PPT; px++)
            #pragma unroll
            for (int op = 0; op < 4; op++)
                scratch[ltid * 16 + px * 4 + op] = acc[px][op];
    }
    __syncthreads();
    if (cg == 0) {
        const int h = h0 + row;
        #pragma unroll
        for (int op = 0; op < 4; op++) {
            const int o0 = 2 * op;
            const float bi0 = __ldg(&bias[o0]);
            const float bi1 = __ldg(&bias[o0 + 1]);
            float4 r0, r1;
            float* pr0 = &r0.x;
            float* pr1 = &r1.x;
            #pragma unroll
            for (int px = 0; px < PPT; px++) {
                float a0, a1, s0, s1;
                unpack2(acc[px][op], a0, a1);
                unpack2(scratch[ltid * 16 + px * 4 + op], s0, s1);
                pr0[px] = a0 + s0 + bi0;
                pr1[px] = a1 + s1 + bi1;
            }
            float* dst0 = &out[((((b * OC + o0) * U_DIM + u) * V_DIM + v) * H_DIM + h) * W_DIM + wbase];
            float* dst1 = &out[((((b * OC + o0 + 1) * U_DIM + u) * V_DIM + v) * H_DIM + h) * W_DIM + wbase];
            *(float4*)dst0 = r0;
            *(float4*)dst1 = r1;
        }
    }
}

extern "C" void kernel_launch(void* const* d_in, const int* in_sizes, int n_in,
                              void* d_out, int out_size)
{
    const float* x    = (const float*)d_in[0];
    const float* conv = (const float*)d_in[1];
    const float* bias = (const float*)d_in[2];
    float* out        = (float*)d_out;

    cudaFuncSetAttribute(conv4d_kernel,
                         cudaFuncAttributeMaxDynamicSharedMemorySize, SMEM_BYTES);

    dim3 grid(H_DIM / TH, U_DIM * V_DIM, 2);   // (6, 49, 2) = 588 blocks
    conv4d_kernel<<<grid, NTHREADS, SMEM_BYTES>>>(x, conv, bias, out);
}